// round 2
// baseline (speedup 1.0000x reference)
#include <cuda_runtime.h>
#include <math.h>

#define NT 4000
#define NS 5000

// ---------------- scratch (device globals; no allocations allowed) ----------
__device__ __align__(16) float g_srcE[25000000];      // exp(relu(src_nv1@src_nv2)) unnormalized [NS,NS]
__device__ __align__(16) float g_vnaE[20000000];      // [NT,NS]
__device__ __align__(16) float g_tgtE[16000000];      // [NT,NT]
__device__ float g_src_inv[NS];
__device__ float g_vna_inv[NT];
__device__ float g_tgt_inv[NT];
__device__ __align__(16) float g_lr[3 * NS * 128];    // source layer results, packed [n,128] (col = b*64+d)
__device__ __align__(16) float g_semb[3 * NT * 128];  // VNA source embeddings
__device__ __align__(16) float g_Y[2 * NS * 128];     // GEMM outputs (support0, support1)
__device__ __align__(16) float g_T[NT * 128];         // target GC output
__device__ __align__(16) float g_xt[NT * 128];        // target running state

// ---------------- pack / unpack ([B,n,64] <-> [n,128]) ----------------------
__global__ void pack_kernel(const float* __restrict__ x, float* __restrict__ xp, int n) {
    int i = blockIdx.x * blockDim.x + threadIdx.x;
    if (i >= n * 128) return;
    int r = i >> 7, c = i & 127, b = c >> 6, d = c & 63;
    xp[i] = x[((size_t)b * n + r) * 64 + d];
}

__global__ void unpack_kernel(const float* __restrict__ xp, float* __restrict__ out, int n) {
    int i = blockIdx.x * blockDim.x + threadIdx.x;
    if (i >= n * 128) return;
    int r = i >> 7, c = i & 127, b = c >> 6, d = c & 63;
    out[((size_t)b * n + r) * 64 + d] = xp[i];
}

// ---------------- adaptive adjacency: E = exp(relu(nv1@nv2)), inv = 1/rowsum
__global__ __launch_bounds__(256)
void adp_kernel(const float* __restrict__ nv1, const float* __restrict__ nv2,
                float* __restrict__ E, float* __restrict__ inv,
                int nrows, int ncols)
{
    __shared__ float v1s[16][30];
    __shared__ float part[8][16];
    const int tid = threadIdx.x;
    const int r0 = blockIdx.x * 16;

    for (int idx = tid; idx < 16 * 30; idx += 256) {
        int r = idx / 30, q = idx % 30;
        v1s[r][q] = (r0 + r < nrows) ? nv1[(size_t)(r0 + r) * 30 + q] : 0.f;
    }
    __syncthreads();

    float psum[16];
#pragma unroll
    for (int r = 0; r < 16; r++) psum[r] = 0.f;

    for (int c = tid; c < ncols; c += 256) {
        float col[30];
#pragma unroll
        for (int q = 0; q < 30; q++) col[q] = nv2[(size_t)q * ncols + c];
#pragma unroll
        for (int r = 0; r < 16; r++) {
            float dot = 0.f;
#pragma unroll
            for (int q = 0; q < 30; q++) dot = fmaf(v1s[r][q], col[q], dot);
            float e = expf(fmaxf(dot, 0.f));
            if (r0 + r < nrows) E[(size_t)(r0 + r) * ncols + c] = e;
            psum[r] += e;
        }
    }
    // deterministic two-stage reduction
    const int lane = tid & 31, wid = tid >> 5;
#pragma unroll
    for (int r = 0; r < 16; r++) {
        float v = psum[r];
#pragma unroll
        for (int off = 16; off > 0; off >>= 1)
            v += __shfl_down_sync(0xffffffffu, v, off);
        if (lane == 0) part[wid][r] = v;
    }
    __syncthreads();
    if (tid < 16 && r0 + tid < nrows) {
        float s = 0.f;
#pragma unroll
        for (int w = 0; w < 8; w++) s += part[w][tid];
        inv[r0 + tid] = 1.0f / s;
    }
}

// ---------------- main GEMM: Y[z][n,128] = A_z[n,m] @ X[m,128] (*invsum row scale for z==1)
__global__ __launch_bounds__(256)
void gc_gemm_kernel(const float* __restrict__ Adense,
                    const float* __restrict__ Eadp,
                    const float* __restrict__ invsum,
                    const float* __restrict__ X,
                    float* __restrict__ Y,
                    int n, int m)
{
    const float* __restrict__ A = (blockIdx.z == 0) ? Adense : Eadp;
    __shared__ float As[64][33];    // +1 pad: conflict-free STS and broadcast LDS
    __shared__ float Xs[32][128];
    const int tid = threadIdx.x;
    const int row0 = blockIdx.x * 64;
    const int tr = tid >> 4;        // 16 row-groups of 4 rows
    const int tc = tid & 15;        // 16 col-groups of 8 cols

    float acc[4][8];
#pragma unroll
    for (int i = 0; i < 4; i++)
#pragma unroll
        for (int j = 0; j < 8; j++) acc[i][j] = 0.f;

    float4 aR[2], xR[4];
    // initial prefetch (k0 = 0)
#pragma unroll
    for (int t = 0; t < 2; t++) {
        int f = tid + t * 256;
        int r = f >> 3, ko = (f & 7) << 2;
        int gr = row0 + r;
        float4 v = make_float4(0.f, 0.f, 0.f, 0.f);
        if (gr < n && ko < m) v = *(const float4*)(A + (size_t)gr * m + ko);
        aR[t] = v;
    }
#pragma unroll
    for (int t = 0; t < 4; t++) {
        int f = tid + t * 256;
        int kr = f >> 5, c4 = (f & 31) << 2;
        float4 v = make_float4(0.f, 0.f, 0.f, 0.f);
        if (kr < m) v = *(const float4*)(X + (size_t)kr * 128 + c4);
        xR[t] = v;
    }

    for (int k0 = 0; k0 < m; k0 += 32) {
        __syncthreads();
#pragma unroll
        for (int t = 0; t < 2; t++) {
            int f = tid + t * 256;
            int r = f >> 3, ko = (f & 7) << 2;
            As[r][ko + 0] = aR[t].x; As[r][ko + 1] = aR[t].y;
            As[r][ko + 2] = aR[t].z; As[r][ko + 3] = aR[t].w;
        }
#pragma unroll
        for (int t = 0; t < 4; t++) {
            int f = tid + t * 256;
            int kr = f >> 5, c4 = (f & 31) << 2;
            *(float4*)&Xs[kr][c4] = xR[t];
        }
        __syncthreads();

        int k1 = k0 + 32;
        if (k1 < m) {   // prefetch next tile into registers (overlaps compute)
#pragma unroll
            for (int t = 0; t < 2; t++) {
                int f = tid + t * 256;
                int r = f >> 3, ko = (f & 7) << 2;
                int gr = row0 + r, gk = k1 + ko;
                float4 v = make_float4(0.f, 0.f, 0.f, 0.f);
                if (gr < n && gk < m) v = *(const float4*)(A + (size_t)gr * m + gk);
                aR[t] = v;
            }
#pragma unroll
            for (int t = 0; t < 4; t++) {
                int f = tid + t * 256;
                int kr = f >> 5, c4 = (f & 31) << 2;
                int gk = k1 + kr;
                float4 v = make_float4(0.f, 0.f, 0.f, 0.f);
                if (gk < m) v = *(const float4*)(X + (size_t)gk * 128 + c4);
                xR[t] = v;
            }
        }

#pragma unroll
        for (int kk = 0; kk < 32; kk++) {
            float av[4];
#pragma unroll
            for (int i = 0; i < 4; i++) av[i] = As[tr * 4 + i][kk];
            float4 xlo = *(const float4*)&Xs[kk][tc * 8];
            float4 xhi = *(const float4*)&Xs[kk][tc * 8 + 4];
            float xv[8] = {xlo.x, xlo.y, xlo.z, xlo.w, xhi.x, xhi.y, xhi.z, xhi.w};
#pragma unroll
            for (int i = 0; i < 4; i++)
#pragma unroll
                for (int j = 0; j < 8; j++)
                    acc[i][j] = fmaf(av[i], xv[j], acc[i][j]);
        }
    }

    float* Yz = Y + (size_t)blockIdx.z * n * 128;
#pragma unroll
    for (int i = 0; i < 4; i++) {
        int gr = row0 + tr * 4 + i;
        if (gr < n) {
            float s = (blockIdx.z == 1) ? invsum[gr] : 1.f;  // fold softmax normalization here
            float4 o0 = make_float4(acc[i][0] * s, acc[i][1] * s, acc[i][2] * s, acc[i][3] * s);
            float4 o1 = make_float4(acc[i][4] * s, acc[i][5] * s, acc[i][6] * s, acc[i][7] * s);
            *(float4*)(Yz + (size_t)gr * 128 + tc * 8)     = o0;
            *(float4*)(Yz + (size_t)gr * 128 + tc * 8 + 4) = o1;
        }
    }
}

// ---------------- GC epilogue: out = [prev +] relu(Y1@W_top + Y2@W_bot + b)
__global__ __launch_bounds__(256)
void gc_epilogue_kernel(const float* __restrict__ Y,
                        const float* __restrict__ W,     // [128,64]
                        const float* __restrict__ bias,  // [64]
                        const float* __restrict__ prev,  // nullable residual
                        float* __restrict__ out, int n)
{
    __shared__ float Ws[128][64];
    __shared__ float Y1s[8][128];
    __shared__ float Y2s[8][128];
    const int tid = threadIdx.x;
    const int r0 = blockIdx.x * 8;
    for (int i = tid; i < 128 * 64; i += 256) Ws[i >> 6][i & 63] = W[i];
    const float* __restrict__ Y2 = Y + (size_t)n * 128;
    for (int i = tid; i < 8 * 128; i += 256) {
        int r = i >> 7, c = i & 127;
        int gr = r0 + r;
        float v1 = 0.f, v2 = 0.f;
        if (gr < n) { v1 = Y[(size_t)gr * 128 + c]; v2 = Y2[(size_t)gr * 128 + c]; }
        Y1s[r][c] = v1; Y2s[r][c] = v2;
    }
    __syncthreads();
    const int c = tid & 127, rg = tid >> 7, d = c & 63, b64 = c & 64;
    const float bv = bias[d];
    for (int rr = rg; rr < 8; rr += 2) {
        int gr = r0 + rr;
        if (gr >= n) break;
        float acc = bv;
#pragma unroll
        for (int k = 0; k < 64; k++) {
            acc = fmaf(Y1s[rr][b64 + k], Ws[k][d], acc);
            acc = fmaf(Y2s[rr][b64 + k], Ws[64 + k][d], acc);
        }
        float g = fmaxf(acc, 0.f);
        out[(size_t)gr * 128 + c] = prev ? (prev[(size_t)gr * 128 + c] + g) : g;
    }
}

// ---------------- gated fusion: x += z*t + (1-z)*s, z = sigmoid(t@Wt + s@Ws + b)
__global__ __launch_bounds__(256)
void fusion_kernel(const float* __restrict__ T, const float* __restrict__ S,
                   const float* __restrict__ Wt, const float* __restrict__ Wsrc,
                   const float* __restrict__ fb, float* __restrict__ xt, int n)
{
    __shared__ float Wts[64][64];
    __shared__ float Wss[64][64];
    __shared__ float Ts[8][128];
    __shared__ float Ss[8][128];
    const int tid = threadIdx.x;
    const int r0 = blockIdx.x * 8;
    for (int i = tid; i < 64 * 64; i += 256) { Wts[i >> 6][i & 63] = Wt[i]; Wss[i >> 6][i & 63] = Wsrc[i]; }
    for (int i = tid; i < 8 * 128; i += 256) {
        int r = i >> 7, c = i & 127;
        int gr = r0 + r;
        float tv = 0.f, sv = 0.f;
        if (gr < n) { tv = T[(size_t)gr * 128 + c]; sv = S[(size_t)gr * 128 + c]; }
        Ts[r][c] = tv; Ss[r][c] = sv;
    }
    __syncthreads();
    const int c = tid & 127, rg = tid >> 7, d = c & 63, b64 = c & 64;
    const float bv = fb[d];
    for (int rr = rg; rr < 8; rr += 2) {
        int gr = r0 + rr;
        if (gr >= n) break;
        float acc = bv;
#pragma unroll
        for (int k = 0; k < 64; k++) {
            acc = fmaf(Ts[rr][b64 + k], Wts[k][d], acc);
            acc = fmaf(Ss[rr][b64 + k], Wss[k][d], acc);
        }
        float z = 1.f / (1.f + expf(-acc));
        float tv = Ts[rr][c], sv = Ss[rr][c];
        xt[(size_t)gr * 128 + c] += z * tv + (1.f - z) * sv;
    }
}

// ---------------- launcher ---------------------------------------------------
extern "C" void kernel_launch(void* const* d_in, const int* in_sizes, int n_in,
                              void* d_out, int out_size)
{
    (void)in_sizes; (void)n_in; (void)out_size;
    const float* A0      = (const float*)d_in[0];
    const float* A1      = (const float*)d_in[1];
    const float* A2      = (const float*)d_in[2];
    const float* x0      = (const float*)d_in[3];
    const float* x1      = (const float*)d_in[4];
    const float* src_nv1 = (const float*)d_in[5];
    const float* src_nv2 = (const float*)d_in[6];
    const float* src_W   = (const float*)d_in[7];
    const float* src_b   = (const float*)d_in[8];
    const float* vna_nv1 = (const float*)d_in[9];
    const float* vna_nv2 = (const float*)d_in[10];
    const float* vna_W   = (const float*)d_in[11];
    const float* vna_b   = (const float*)d_in[12];
    const float* tgt_nv1 = (const float*)d_in[13];
    const float* tgt_nv2 = (const float*)d_in[14];
    const float* tgt_W   = (const float*)d_in[15];
    const float* tgt_b   = (const float*)d_in[16];
    const float* fus_Wt  = (const float*)d_in[17];
    const float* fus_Ws  = (const float*)d_in[18];
    const float* fus_b   = (const float*)d_in[19];

    float *srcE, *vnaE, *tgtE, *src_inv, *vna_inv, *tgt_inv, *lr, *semb, *Yb, *Tb, *xtb;
    cudaGetSymbolAddress((void**)&srcE,    g_srcE);
    cudaGetSymbolAddress((void**)&vnaE,    g_vnaE);
    cudaGetSymbolAddress((void**)&tgtE,    g_tgtE);
    cudaGetSymbolAddress((void**)&src_inv, g_src_inv);
    cudaGetSymbolAddress((void**)&vna_inv, g_vna_inv);
    cudaGetSymbolAddress((void**)&tgt_inv, g_tgt_inv);
    cudaGetSymbolAddress((void**)&lr,      g_lr);
    cudaGetSymbolAddress((void**)&semb,    g_semb);
    cudaGetSymbolAddress((void**)&Yb,      g_Y);
    cudaGetSymbolAddress((void**)&Tb,      g_T);
    cudaGetSymbolAddress((void**)&xtb,     g_xt);

    // pack inputs into [n,128] (col = b*64+d)
    pack_kernel<<<(NS * 128 + 255) / 256, 256>>>(x1, lr, NS);
    pack_kernel<<<(NT * 128 + 255) / 256, 256>>>(x0, xtb, NT);

    // adaptive adjacencies (unnormalized exp + row inverse sums)
    adp_kernel<<<(NS + 15) / 16, 256>>>(src_nv1, src_nv2, srcE, src_inv, NS, NS);
    adp_kernel<<<(NT + 15) / 16, 256>>>(vna_nv1, vna_nv2, vnaE, vna_inv, NT, NS);
    adp_kernel<<<(NT + 15) / 16, 256>>>(tgt_nv1, tgt_nv2, tgtE, tgt_inv, NT, NT);

    // ---- Source GC block (2 residual layers) ----
    dim3 gsrc((NS + 63) / 64, 1, 2);
    for (int i = 0; i < 2; i++) {
        gc_gemm_kernel<<<gsrc, 256>>>(A2, srcE, src_inv, lr + (size_t)i * NS * 128, Yb, NS, NS);
        gc_epilogue_kernel<<<(NS + 7) / 8, 256>>>(Yb, src_W + i * 8192, src_b + i * 64,
                                                  lr + (size_t)i * NS * 128,
                                                  lr + (size_t)(i + 1) * NS * 128, NS);
    }

    // ---- VNA block (3 layers, Ns -> Nt, no residual) ----
    dim3 gtgt((NT + 63) / 64, 1, 2);
    for (int i = 0; i < 3; i++) {
        gc_gemm_kernel<<<gtgt, 256>>>(A1, vnaE, vna_inv, lr + (size_t)i * NS * 128, Yb, NT, NS);
        gc_epilogue_kernel<<<(NT + 7) / 8, 256>>>(Yb, vna_W + i * 8192, vna_b + i * 64,
                                                  nullptr, semb + (size_t)i * NT * 128, NT);
    }

    // ---- Target GC block with gated fusion ----
    for (int i = 0; i < 3; i++) {
        gc_gemm_kernel<<<gtgt, 256>>>(A0, tgtE, tgt_inv, xtb, Yb, NT, NT);
        gc_epilogue_kernel<<<(NT + 7) / 8, 256>>>(Yb, tgt_W + i * 8192, tgt_b + i * 64,
                                                  nullptr, Tb, NT);
        fusion_kernel<<<(NT + 7) / 8, 256>>>(Tb, semb + (size_t)i * NT * 128,
                                             fus_Wt + i * 4096, fus_Ws + i * 4096,
                                             fus_b + i * 64, xtb, NT);
    }

    unpack_kernel<<<(NT * 128 + 255) / 256, 256>>>(xtb, (float*)d_out, NT);
}

// round 4
// speedup vs baseline: 2.4492x; 2.4492x over previous
#include <cuda_runtime.h>
#include <cuda_bf16.h>
#include <math.h>
#include <stdint.h>

#define NT 4000
#define NS 5000

// ===================== scratch (device globals) =============================
__device__ __align__(16) unsigned short g_A0h[16000000], g_A0l[16000000];
__device__ __align__(16) unsigned short g_A1h[20000000], g_A1l[20000000];
__device__ __align__(16) unsigned short g_A2h[25000000], g_A2l[25000000];
__device__ __align__(16) unsigned short g_Esh[25000000], g_Esl[25000000];
__device__ __align__(16) unsigned short g_Evh[20000000], g_Evl[20000000];
__device__ __align__(16) unsigned short g_Eth[16000000], g_Etl[16000000];
__device__ __align__(16) unsigned short g_Xth[128 * NS], g_Xtl[128 * NS];
__device__ float g_src_inv[NS];
__device__ float g_vna_inv[NT];
__device__ float g_tgt_inv[NT];
__device__ __align__(16) float g_lr[3 * NS * 128];
__device__ __align__(16) float g_semb[3 * NT * 128];
__device__ __align__(16) float g_Y[2 * NS * 128];
__device__ __align__(16) float g_T[NT * 128];
__device__ __align__(16) float g_xt[NT * 128];

// ===================== PTX helpers (sm_80+ only; NO tcgen05) ================
__device__ __forceinline__ uint32_t smem_u32(const void* p) {
    uint32_t a;
    asm("{ .reg .u64 t; cvta.to.shared.u64 t, %1; cvt.u32.u64 %0, t; }" : "=r"(a) : "l"(p));
    return a;
}

#define CP_ASYNC16(saddr, gaddr, sz) \
    asm volatile("cp.async.ca.shared.global [%0], [%1], 16, %2;" \
        :: "r"(saddr), "l"(gaddr), "r"(sz))
#define CP_COMMIT() asm volatile("cp.async.commit_group;" ::: "memory")
#define CP_WAIT1()  asm volatile("cp.async.wait_group 1;" ::: "memory")

#define LDSM4(r, a) \
    asm volatile("ldmatrix.sync.aligned.m8n8.x4.shared.b16 {%0,%1,%2,%3}, [%4];" \
        : "=r"((r)[0]), "=r"((r)[1]), "=r"((r)[2]), "=r"((r)[3]) : "r"(a))

#define MMA_BF16(c, A, b0, b1) \
    asm volatile("mma.sync.aligned.m16n8k16.row.col.f32.bf16.bf16.f32 " \
        "{%0,%1,%2,%3},{%4,%5,%6,%7},{%8,%9},{%0,%1,%2,%3};" \
        : "+f"((c)[0]), "+f"((c)[1]), "+f"((c)[2]), "+f"((c)[3]) \
        : "r"((A)[0]), "r"((A)[1]), "r"((A)[2]), "r"((A)[3]), "r"(b0), "r"(b1))

// ===================== pack / unpack ========================================
__global__ void pack_kernel(const float* __restrict__ x, float* __restrict__ xp, int n) {
    int i = blockIdx.x * blockDim.x + threadIdx.x;
    if (i >= n * 128) return;
    int r = i >> 7, c = i & 127, b = c >> 6, d = c & 63;
    xp[i] = x[((size_t)b * n + r) * 64 + d];
}
__global__ void unpack_kernel(const float* __restrict__ xp, float* __restrict__ out, int n) {
    int i = blockIdx.x * blockDim.x + threadIdx.x;
    if (i >= n * 128) return;
    int r = i >> 7, c = i & 127, b = c >> 6, d = c & 63;
    out[((size_t)b * n + r) * 64 + d] = xp[i];
}

// ===================== fp32 -> bf16 hi/lo split =============================
__global__ void split_kernel(const float* __restrict__ A,
                             unsigned short* __restrict__ H,
                             unsigned short* __restrict__ L, int n4) {
    int i = blockIdx.x * blockDim.x + threadIdx.x;
    if (i >= n4) return;
    float4 v = ((const float4*)A)[i];
    __nv_bfloat16 h0 = __float2bfloat16(v.x), h1 = __float2bfloat16(v.y);
    __nv_bfloat16 h2 = __float2bfloat16(v.z), h3 = __float2bfloat16(v.w);
    __nv_bfloat16 l0 = __float2bfloat16(v.x - __bfloat162float(h0));
    __nv_bfloat16 l1 = __float2bfloat16(v.y - __bfloat162float(h1));
    __nv_bfloat16 l2 = __float2bfloat16(v.z - __bfloat162float(h2));
    __nv_bfloat16 l3 = __float2bfloat16(v.w - __bfloat162float(h3));
    ushort4 hv, lv;
    hv.x = __bfloat16_as_ushort(h0); hv.y = __bfloat16_as_ushort(h1);
    hv.z = __bfloat16_as_ushort(h2); hv.w = __bfloat16_as_ushort(h3);
    lv.x = __bfloat16_as_ushort(l0); lv.y = __bfloat16_as_ushort(l1);
    lv.z = __bfloat16_as_ushort(l2); lv.w = __bfloat16_as_ushort(l3);
    ((ushort4*)H)[i] = hv;
    ((ushort4*)L)[i] = lv;
}

// ===================== adaptive adjacency (bf16 hi/lo out) ==================
__global__ __launch_bounds__(256)
void adp_kernel(const float* __restrict__ nv1, const float* __restrict__ nv2,
                unsigned short* __restrict__ Eh, unsigned short* __restrict__ El,
                float* __restrict__ inv, int nrows, int ncols)
{
    __shared__ float v1s[8][30];
    __shared__ float part[8][8];
    const int tid = threadIdx.x;
    const int r0 = blockIdx.x * 8;
    if (tid < 240) v1s[tid / 30][tid % 30] = nv1[(size_t)(r0 + tid / 30) * 30 + tid % 30];
    __syncthreads();

    float psum[8];
#pragma unroll
    for (int r = 0; r < 8; r++) psum[r] = 0.f;

    for (int c = tid; c < ncols; c += 256) {
        float col[30];
#pragma unroll
        for (int q = 0; q < 30; q++) col[q] = nv2[(size_t)q * ncols + c];
#pragma unroll
        for (int r = 0; r < 8; r++) {
            float dot = 0.f;
#pragma unroll
            for (int q = 0; q < 30; q++) dot = fmaf(v1s[r][q], col[q], dot);
            float t = fmaxf(dot, 0.f) * 1.4426950408889634f;
            float e;
            asm("ex2.approx.f32 %0, %1;" : "=f"(e) : "f"(t));
            __nv_bfloat16 h = __float2bfloat16(e);
            size_t idx = (size_t)(r0 + r) * ncols + c;
            Eh[idx] = __bfloat16_as_ushort(h);
            El[idx] = __bfloat16_as_ushort(__float2bfloat16(e - __bfloat162float(h)));
            psum[r] += e;
        }
    }
    const int lane = tid & 31, wid = tid >> 5;
#pragma unroll
    for (int r = 0; r < 8; r++) {
        float v = psum[r];
#pragma unroll
        for (int off = 16; off > 0; off >>= 1) v += __shfl_down_sync(0xffffffffu, v, off);
        if (lane == 0) part[wid][r] = v;
    }
    __syncthreads();
    if (tid < 8) {
        float s = 0.f;
#pragma unroll
        for (int w = 0; w < 8; w++) s += part[w][tid];
        inv[r0 + tid] = 1.0f / s;
    }
}

// ===================== X^T prep: [m,128] fp32 -> [128,m] bf16 hi/lo =========
__global__ __launch_bounds__(256)
void xt_prep(const float* __restrict__ X, unsigned short* __restrict__ Xh,
             unsigned short* __restrict__ Xl, int m)
{
    __shared__ float t[32][33];
    const int mb = blockIdx.x * 32, cb = blockIdx.y * 32;
    const int lx = threadIdx.x & 31, ly = threadIdx.x >> 5;
#pragma unroll
    for (int yy = ly; yy < 32; yy += 8) {
        int gm = mb + yy;
        t[yy][lx] = (gm < m) ? X[(size_t)gm * 128 + cb + lx] : 0.f;
    }
    __syncthreads();
#pragma unroll
    for (int yy = ly; yy < 32; yy += 8) {
        int c = cb + yy, gm = mb + lx;
        if (gm < m) {
            float v = t[lx][yy];
            __nv_bfloat16 h = __float2bfloat16(v);
            Xh[(size_t)c * m + gm] = __bfloat16_as_ushort(h);
            Xl[(size_t)c * m + gm] = __bfloat16_as_ushort(__float2bfloat16(v - __bfloat162float(h)));
        }
    }
}

// ===================== HMMA GEMM ============================================
// Y[z][n,128] = A_z[n,m] @ X[m,128]; fp32-accurate via bf16 hi/lo 3-pass.
// z==1 applies invsum row scale (softmax normalization folded).
// Block: 64(M) x 128(N), KT=64, 8 warps (2m x 4n), warp tile 32x32.
#define BM 64
#define GKT 64
#define STAGE_B 49152   // Ah 8K | Al 8K | Bh 16K | Bl 16K
#define SMEM_GEMM (2 * STAGE_B)

__device__ __forceinline__ void stage_load(
    uint32_t sdst, const unsigned short* __restrict__ Ah,
    const unsigned short* __restrict__ Al,
    const unsigned short* __restrict__ Xh, const unsigned short* __restrict__ Xl,
    int row0, int kbase, int n, int m, int tid)
{
    // A hi/lo: 64 rows x 64 k (8 x 16B chunks per row)
#pragma unroll
    for (int t = 0; t < 2; t++) {
        int id = tid + t * 256;
        int r = id >> 3, kc = id & 7;
        int gr = row0 + r, gk = kbase + kc * 8;
        bool v = (gr < n) && (gk < m);
        size_t gi = (size_t)(v ? gr : 0) * m + (v ? gk : 0);
        uint32_t off = r * 128 + kc * 16;
        uint32_t sw = off ^ ((off >> 3) & 0x70);
        unsigned sz = v ? 16u : 0u;
        CP_ASYNC16(sdst + sw, Ah + gi, sz);
        CP_ASYNC16(sdst + 8192 + sw, Al + gi, sz);
    }
    // B hi/lo: 128 rows (n-cols) x 64 k
#pragma unroll
    for (int t = 0; t < 4; t++) {
        int id = tid + t * 256;
        int r = id >> 3, kc = id & 7;
        int gk = kbase + kc * 8;
        bool v = (gk < m);
        size_t gi = (size_t)r * m + (v ? gk : 0);
        uint32_t off = r * 128 + kc * 16;
        uint32_t sw = off ^ ((off >> 3) & 0x70);
        unsigned sz = v ? 16u : 0u;
        CP_ASYNC16(sdst + 16384 + sw, Xh + gi, sz);
        CP_ASYNC16(sdst + 32768 + sw, Xl + gi, sz);
    }
}

__global__ __launch_bounds__(256, 2)
void hmma_gemm(const unsigned short* __restrict__ A0h, const unsigned short* __restrict__ A0l,
               const unsigned short* __restrict__ E1h, const unsigned short* __restrict__ E1l,
               const float* __restrict__ invsum,
               const unsigned short* __restrict__ Xh, const unsigned short* __restrict__ Xl,
               float* __restrict__ Y, int n, int m)
{
    extern __shared__ __align__(128) char smem[];
    const uint32_t sb = smem_u32(smem);
    const int tid = threadIdx.x, lane = tid & 31, wid = tid >> 5;
    const int wm = wid >> 2, wn = wid & 3;
    const unsigned short* __restrict__ Ah = blockIdx.z ? E1h : A0h;
    const unsigned short* __restrict__ Al = blockIdx.z ? E1l : A0l;
    const int row0 = blockIdx.x * BM;
    const int ktn = (m + GKT - 1) / GKT;

    float acc[2][4][4];
#pragma unroll
    for (int i = 0; i < 2; i++)
#pragma unroll
        for (int j = 0; j < 4; j++)
#pragma unroll
            for (int q = 0; q < 4; q++) acc[i][j][q] = 0.f;

    // ldmatrix lane addressing (row offset + xor term independent of k chunk)
    uint32_t arow[2], axor[2];
#pragma unroll
    for (int mt = 0; mt < 2; mt++) {
        int r = wm * 32 + mt * 16 + (lane & 7) + (((lane >> 3) & 1) << 3);
        arow[mt] = (uint32_t)r * 128;
        axor[mt] = ((uint32_t)r * 16) & 0x70;
    }
    const uint32_t akbs = ((lane >> 4) & 1) * 16;
    uint32_t brow[2], bxor[2];
#pragma unroll
    for (int bt = 0; bt < 2; bt++) {
        int r = wn * 32 + bt * 16 + (lane & 7) + (((lane >> 4) & 1) << 3);
        brow[bt] = (uint32_t)r * 128;
        bxor[bt] = ((uint32_t)r * 16) & 0x70;
    }
    const uint32_t bkbs = ((lane >> 3) & 1) * 16;

    // prologue
    stage_load(sb, Ah, Al, Xh, Xl, row0, 0, n, m, tid);
    CP_COMMIT();

    for (int kt = 0; kt < ktn; kt++) {
        if (kt + 1 < ktn)
            stage_load(sb + ((kt + 1) & 1) * STAGE_B, Ah, Al, Xh, Xl,
                       row0, (kt + 1) * GKT, n, m, tid);
        CP_COMMIT();
        CP_WAIT1();
        __syncthreads();

        const uint32_t stb = sb + (kt & 1) * STAGE_B;
#pragma unroll
        for (int ks = 0; ks < 4; ks++) {
            const uint32_t kb = ks * 32;
            uint32_t fah[2][4], fal[2][4], fbh[2][4], fbl[2][4];
#pragma unroll
            for (int mt = 0; mt < 2; mt++) {
                uint32_t ad = stb + arow[mt] + ((kb + akbs) ^ axor[mt]);
                LDSM4(fah[mt], ad);
                LDSM4(fal[mt], ad + 8192);
            }
#pragma unroll
            for (int bt = 0; bt < 2; bt++) {
                uint32_t bd = stb + 16384 + brow[bt] + ((kb + bkbs) ^ bxor[bt]);
                LDSM4(fbh[bt], bd);
                LDSM4(fbl[bt], bd + 16384);
            }
#pragma unroll
            for (int mt = 0; mt < 2; mt++) {
#pragma unroll
                for (int nt = 0; nt < 4; nt++) {
                    const int g = nt >> 1, h = (nt & 1) << 1;
                    MMA_BF16(acc[mt][nt], fah[mt], fbh[g][h], fbh[g][h + 1]);
                    MMA_BF16(acc[mt][nt], fah[mt], fbl[g][h], fbl[g][h + 1]);
                    MMA_BF16(acc[mt][nt], fal[mt], fbh[g][h], fbh[g][h + 1]);
                }
            }
        }
        __syncthreads();
    }

    // ---- store ----
    float* __restrict__ Yz = Y + (size_t)blockIdx.z * n * 128;
#pragma unroll
    for (int mt = 0; mt < 2; mt++) {
        int gr0 = row0 + wm * 32 + mt * 16 + (lane >> 2);
        int gr1 = gr0 + 8;
        float s0 = 1.f, s1 = 1.f;
        if (blockIdx.z) {
            if (gr0 < n) s0 = invsum[gr0];
            if (gr1 < n) s1 = invsum[gr1];
        }
#pragma unroll
        for (int nt = 0; nt < 4; nt++) {
            int col = wn * 32 + nt * 8 + ((lane & 3) << 1);
            if (gr0 < n) {
                float2 o = make_float2(acc[mt][nt][0] * s0, acc[mt][nt][1] * s0);
                *(float2*)(Yz + (size_t)gr0 * 128 + col) = o;
            }
            if (gr1 < n) {
                float2 o = make_float2(acc[mt][nt][2] * s1, acc[mt][nt][3] * s1);
                *(float2*)(Yz + (size_t)gr1 * 128 + col) = o;
            }
        }
    }
}

// ===================== GC epilogue ==========================================
__global__ __launch_bounds__(256)
void gc_epilogue_kernel(const float* __restrict__ Y, const float* __restrict__ W,
                        const float* __restrict__ bias, const float* __restrict__ prev,
                        float* __restrict__ out, int n)
{
    __shared__ float Ws[128][64];
    __shared__ float Y1s[8][128];
    __shared__ float Y2s[8][128];
    const int tid = threadIdx.x;
    const int r0 = blockIdx.x * 8;
    for (int i = tid; i < 128 * 64; i += 256) Ws[i >> 6][i & 63] = W[i];
    const float* __restrict__ Y2 = Y + (size_t)n * 128;
    for (int i = tid; i < 8 * 128; i += 256) {
        int r = i >> 7, c = i & 127;
        int gr = r0 + r;
        float v1 = 0.f, v2 = 0.f;
        if (gr < n) { v1 = Y[(size_t)gr * 128 + c]; v2 = Y2[(size_t)gr * 128 + c]; }
        Y1s[r][c] = v1; Y2s[r][c] = v2;
    }
    __syncthreads();
    const int c = tid & 127, rg = tid >> 7, d = c & 63, b64 = c & 64;
    const float bv = bias[d];
    for (int rr = rg; rr < 8; rr += 2) {
        int gr = r0 + rr;
        if (gr >= n) break;
        float acc = bv;
#pragma unroll
        for (int k = 0; k < 64; k++) {
            acc = fmaf(Y1s[rr][b64 + k], Ws[k][d], acc);
            acc = fmaf(Y2s[rr][b64 + k], Ws[64 + k][d], acc);
        }
        float g = fmaxf(acc, 0.f);
        out[(size_t)gr * 128 + c] = prev ? (prev[(size_t)gr * 128 + c] + g) : g;
    }
}

// ===================== gated fusion =========================================
__global__ __launch_bounds__(256)
void fusion_kernel(const float* __restrict__ T, const float* __restrict__ S,
                   const float* __restrict__ Wt, const float* __restrict__ Wsrc,
                   const float* __restrict__ fb, float* __restrict__ xt, int n)
{
    __shared__ float Wts[64][64];
    __shared__ float Wss[64][64];
    __shared__ float Ts[8][128];
    __shared__ float Ss[8][128];
    const int tid = threadIdx.x;
    const int r0 = blockIdx.x * 8;
    for (int i = tid; i < 64 * 64; i += 256) { Wts[i >> 6][i & 63] = Wt[i]; Wss[i >> 6][i & 63] = Wsrc[i]; }
    for (int i = tid; i < 8 * 128; i += 256) {
        int r = i >> 7, c = i & 127;
        int gr = r0 + r;
        float tv = 0.f, sv = 0.f;
        if (gr < n) { tv = T[(size_t)gr * 128 + c]; sv = S[(size_t)gr * 128 + c]; }
        Ts[r][c] = tv; Ss[r][c] = sv;
    }
    __syncthreads();
    const int c = tid & 127, rg = tid >> 7, d = c & 63, b64 = c & 64;
    const float bv = fb[d];
    for (int rr = rg; rr < 8; rr += 2) {
        int gr = r0 + rr;
        if (gr >= n) break;
        float acc = bv;
#pragma unroll
        for (int k = 0; k < 64; k++) {
            acc = fmaf(Ts[rr][b64 + k], Wts[k][d], acc);
            acc = fmaf(Ss[rr][b64 + k], Wss[k][d], acc);
        }
        float z = 1.f / (1.f + expf(-acc));
        xt[(size_t)gr * 128 + c] += z * Ts[rr][c] + (1.f - z) * Ss[rr][c];
    }
}

// ===================== launcher =============================================
extern "C" void kernel_launch(void* const* d_in, const int* in_sizes, int n_in,
                              void* d_out, int out_size)
{
    (void)in_sizes; (void)n_in; (void)out_size;
    const float* A0      = (const float*)d_in[0];
    const float* A1      = (const float*)d_in[1];
    const float* A2      = (const float*)d_in[2];
    const float* x0      = (const float*)d_in[3];
    const float* x1      = (const float*)d_in[4];
    const float* src_nv1 = (const float*)d_in[5];
    const float* src_nv2 = (const float*)d_in[6];
    const float* src_W   = (const float*)d_in[7];
    const float* src_b   = (const float*)d_in[8];
    const float* vna_nv1 = (const float*)d_in[9];
    const float* vna_nv2 = (const float*)d_in[10];
    const float* vna_W   = (const float*)d_in[11];
    const float* vna_b   = (const float*)d_in[12];
    const float* tgt_nv1 = (const float*)d_in[13];
    const float* tgt_nv2 = (const float*)d_in[14];
    const float* tgt_W   = (const float*)d_in[15];
    const float* tgt_b   = (const float*)d_in[16];
    const float* fus_Wt  = (const float*)d_in[17];
    const float* fus_Ws  = (const float*)d_in[18];
    const float* fus_b   = (const float*)d_in[19];

    unsigned short *A0h, *A0l, *A1h, *A1l, *A2h, *A2l;
    unsigned short *Esh, *Esl, *Evh, *Evl, *Eth, *Etl, *Xth, *Xtl;
    float *src_inv, *vna_inv, *tgt_inv, *lr, *semb, *Yb, *Tb, *xtb;
    cudaGetSymbolAddress((void**)&A0h, g_A0h); cudaGetSymbolAddress((void**)&A0l, g_A0l);
    cudaGetSymbolAddress((void**)&A1h, g_A1h); cudaGetSymbolAddress((void**)&A1l, g_A1l);
    cudaGetSymbolAddress((void**)&A2h, g_A2h); cudaGetSymbolAddress((void**)&A2l, g_A2l);
    cudaGetSymbolAddress((void**)&Esh, g_Esh); cudaGetSymbolAddress((void**)&Esl, g_Esl);
    cudaGetSymbolAddress((void**)&Evh, g_Evh); cudaGetSymbolAddress((void**)&Evl, g_Evl);
    cudaGetSymbolAddress((void**)&Eth, g_Eth); cudaGetSymbolAddress((void**)&Etl, g_Etl);
    cudaGetSymbolAddress((void**)&Xth, g_Xth); cudaGetSymbolAddress((void**)&Xtl, g_Xtl);
    cudaGetSymbolAddress((void**)&src_inv, g_src_inv);
    cudaGetSymbolAddress((void**)&vna_inv, g_vna_inv);
    cudaGetSymbolAddress((void**)&tgt_inv, g_tgt_inv);
    cudaGetSymbolAddress((void**)&lr,   g_lr);
    cudaGetSymbolAddress((void**)&semb, g_semb);
    cudaGetSymbolAddress((void**)&Yb,   g_Y);
    cudaGetSymbolAddress((void**)&Tb,   g_T);
    cudaGetSymbolAddress((void**)&xtb,  g_xt);

    cudaFuncSetAttribute(hmma_gemm, cudaFuncAttributeMaxDynamicSharedMemorySize, SMEM_GEMM);

    // pack inputs into [n,128] (col = b*64+d)
    pack_kernel<<<(NS * 128 + 255) / 256, 256>>>(x1, lr, NS);
    pack_kernel<<<(NT * 128 + 255) / 256, 256>>>(x0, xtb, NT);

    // dense adjacency hi/lo splits
    split_kernel<<<(NT * NT / 4 + 255) / 256, 256>>>(A0, A0h, A0l, NT * NT / 4);
    split_kernel<<<(NT * NS / 4 + 255) / 256, 256>>>(A1, A1h, A1l, NT * NS / 4);
    split_kernel<<<(NS * NS / 4 + 255) / 256, 256>>>(A2, A2h, A2l, NS * NS / 4);

    // adaptive adjacencies (unnormalized exp hi/lo + inverse row sums)
    adp_kernel<<<NS / 8, 256>>>(src_nv1, src_nv2, Esh, Esl, src_inv, NS, NS);
    adp_kernel<<<NT / 8, 256>>>(vna_nv1, vna_nv2, Evh, Evl, vna_inv, NT, NS);
    adp_kernel<<<NT / 8, 256>>>(tgt_nv1, tgt_nv2, Eth, Etl, tgt_inv, NT, NT);

    const int tilesS = (NS + BM - 1) / BM;   // 79
    const int tilesT = (NT + BM - 1) / BM;   // 63
    dim3 xg5((NS + 31) / 32, 4), xg4((NT + 31) / 32, 4);

    // ---- Source GC block (2 residual layers) ----
    for (int i = 0; i < 2; i++) {
        xt_prep<<<xg5, 256>>>(lr + (size_t)i * NS * 128, Xth, Xtl, NS);
        hmma_gemm<<<dim3(tilesS, 1, 2), 256, SMEM_GEMM>>>(A2h, A2l, Esh, Esl, src_inv,
                                                          Xth, Xtl, Yb, NS, NS);
        gc_epilogue_kernel<<<(NS + 7) / 8, 256>>>(Yb, src_W + i * 8192, src_b + i * 64,
                                                  lr + (size_t)i * NS * 128,
                                                  lr + (size_t)(i + 1) * NS * 128, NS);
    }

    // ---- VNA block (3 layers, Ns -> Nt) ----
    for (int i = 0; i < 3; i++) {
        xt_prep<<<xg5, 256>>>(lr + (size_t)i * NS * 128, Xth, Xtl, NS);
        hmma_gemm<<<dim3(tilesT, 1, 2), 256, SMEM_GEMM>>>(A1h, A1l, Evh, Evl, vna_inv,
                                                          Xth, Xtl, Yb, NT, NS);
        gc_epilogue_kernel<<<(NT + 7) / 8, 256>>>(Yb, vna_W + i * 8192, vna_b + i * 64,
                                                  nullptr, semb + (size_t)i * NT * 128, NT);
    }

    // ---- Target GC block with gated fusion ----
    for (int i = 0; i < 3; i++) {
        xt_prep<<<xg4, 256>>>(xtb, Xth, Xtl, NT);
        hmma_gemm<<<dim3(tilesT, 1, 2), 256, SMEM_GEMM>>>(A0h, A0l, Eth, Etl, tgt_inv,
                                                          Xth, Xtl, Yb, NT, NT);
        gc_epilogue_kernel<<<(NT + 7) / 8, 256>>>(Yb, tgt_W + i * 8192, tgt_b + i * 64,
                                                  nullptr, Tb, NT);
        fusion_kernel<<<(NT + 7) / 8, 256>>>(Tb, semb + (size_t)i * NT * 128,
                                             fus_Wt + i * 4096, fus_Ws + i * 4096,
                                             fus_b + i * 64, xtb, NT);
    }

    unpack_kernel<<<(NT * 128 + 255) / 256, 256>>>(xtb, (float*)d_out, NT);
}